// round 10
// baseline (speedup 1.0000x reference)
#include <cuda_runtime.h>
#include <math.h>
#include <stdint.h>

#define NI 16
#define CD 1024
#define PD 1024
#define KC 32
#define EPSN 1e-12f

// ---- scratch (static; no allocations allowed) ----
__device__ float g_ar[NI * KC * PD];     // softmax(a)*r  (kb's B operand)
__device__ float g_asp[NI * KC * 32];    // asum partials (ptile x warp)
__device__ float g_v[NI * KC * CD];      // raw vlad gemm D
__device__ unsigned g_ctr[NI];           // per-image completion tickets (self-resetting)

__device__ __forceinline__ uint32_t s2u(const void* p) {
    uint32_t a;
    asm("{ .reg .u64 t; cvta.to.shared.u64 t, %1; cvt.u32.u64 %0, t; }" : "=r"(a) : "l"(p));
    return a;
}

#define CPA16(d, s) asm volatile("cp.async.cg.shared.global [%0], [%1], 16;" :: "r"(d), "l"(s))
#define CPC()  asm volatile("cp.async.commit_group;")
#define CPW1() asm volatile("cp.async.wait_group 1;")
#define CPW0() asm volatile("cp.async.wait_group 0;")

// tf32 m16n8k8 row.col: D += A*B  (A: 4 regs, B: 2 regs, D: 4 floats)
__device__ __forceinline__ void mma8(float* d, const uint32_t* a, const uint32_t* b) {
    asm volatile(
        "mma.sync.aligned.m16n8k8.row.col.f32.tf32.tf32.f32 "
        "{%0,%1,%2,%3}, {%4,%5,%6,%7}, {%8,%9}, {%0,%1,%2,%3};"
        : "+f"(d[0]), "+f"(d[1]), "+f"(d[2]), "+f"(d[3])
        : "r"(a[0]), "r"(a[1]), "r"(a[2]), "r"(a[3]), "r"(b[0]), "r"(b[1]));
}

// =====================================================================
// ka: logits GEMM + per-pixel norm + softmax, fused.
//   D[k=32, p=128] = sum_c w[k,c] * x[c,p]
//   grid (8 ptiles, 16 n), 256 threads = 2 warpgroups (c-split).
// =====================================================================
#define KA_XSF 4352              // 32*136 floats per buffer
#define KA_WSF 1152              // 32*36 floats per buffer
#define KA_SMEM ((4 * KA_XSF + 4 * KA_WSF) * 4)

__global__ void __launch_bounds__(256, 1) ka(const float* __restrict__ x,
                                             const float* __restrict__ w) {
    extern __shared__ float sm[];
    __shared__ float ssqs[128];
    const int tid = threadIdx.x;
    const int wg = tid >> 7, wtid = tid & 127;
    const int lane = tid & 31, wp = wtid >> 5;
    const int qid = lane >> 2, qlane = lane & 3;
    const int ptile = blockIdx.x, n = blockIdx.y, pbase = ptile * 128;
    const float* xn = x + (size_t)n * CD * PD + pbase;
    const uint32_t smu = s2u(sm);

    float d[2][4][4];
#pragma unroll
    for (int mi = 0; mi < 2; mi++)
#pragma unroll
        for (int ni = 0; ni < 4; ni++)
#pragma unroll
            for (int r = 0; r < 4; r++) d[mi][ni][r] = 0.f;
    float ssq = 0.f;

#define KA_LD(gch, buf) do { \
        const float* _x = xn + (size_t)(gch) * 32 * PD; \
        uint32_t _xd = smu + (unsigned)((wg * 2 + (buf)) * KA_XSF) * 4u; \
        _Pragma("unroll") \
        for (int i = 0; i < 8; i++) { \
            int idx = wtid + i * 128, c = idx >> 5, p4 = idx & 31; \
            CPA16(_xd + (unsigned)(c * 136 + p4 * 4) * 4u, _x + (size_t)c * PD + p4 * 4); \
        } \
        const float* _w = w + (gch) * 32; \
        uint32_t _wd = smu + (unsigned)(4 * KA_XSF + (wg * 2 + (buf)) * KA_WSF) * 4u; \
        _Pragma("unroll") \
        for (int i = 0; i < 2; i++) { \
            int idx = wtid + i * 128, k = idx >> 3, c4 = idx & 7; \
            CPA16(_wd + (unsigned)(k * 36 + c4 * 4) * 4u, _w + (size_t)k * CD + c4 * 4); \
        } \
        CPC(); \
    } while (0)

    KA_LD(wg * 16 + 0, 0);
    KA_LD(wg * 16 + 1, 1);

    for (int ch = 0; ch < 16; ch++) {
        const int buf = ch & 1;
        if (ch < 15) CPW1(); else CPW0();
        __syncthreads();
        const float* xsb = sm + (wg * 2 + buf) * KA_XSF;
        const float* wsb = sm + 4 * KA_XSF + (wg * 2 + buf) * KA_WSF;
#pragma unroll
        for (int c = 0; c < 32; c++) {
            float f = xsb[c * 136 + wtid];
            ssq = fmaf(f, f, ssq);
        }
#pragma unroll
        for (int s = 0; s < 4; s++) {
            uint32_t a[2][4], b[4][2];
            const int c0 = s * 8 + qlane;
#pragma unroll
            for (int mi = 0; mi < 2; mi++) {
                const int r0 = mi * 16 + qid;
                a[mi][0] = __float_as_uint(wsb[r0 * 36 + c0]);
                a[mi][1] = __float_as_uint(wsb[(r0 + 8) * 36 + c0]);
                a[mi][2] = __float_as_uint(wsb[r0 * 36 + c0 + 4]);
                a[mi][3] = __float_as_uint(wsb[(r0 + 8) * 36 + c0 + 4]);
            }
#pragma unroll
            for (int ni = 0; ni < 4; ni++) {
                const int pc = wp * 32 + ni * 8 + qid;
                b[ni][0] = __float_as_uint(xsb[c0 * 136 + pc]);
                b[ni][1] = __float_as_uint(xsb[(c0 + 4) * 136 + pc]);
            }
#pragma unroll
            for (int mi = 0; mi < 2; mi++)
#pragma unroll
                for (int ni = 0; ni < 4; ni++) mma8(d[mi][ni], a[mi], b[ni]);
        }
        __syncthreads();
        if (ch + 2 < 16) KA_LD(wg * 16 + ch + 2, buf);
    }
#undef KA_LD

    // ---- combine wg partial logits in smem: Ls[32 k][136] ----
    float (*Ls)[136] = (float (*)[136])sm;
    if (wg == 1) {
#pragma unroll
        for (int mi = 0; mi < 2; mi++)
#pragma unroll
            for (int ni = 0; ni < 4; ni++) {
                const int px = wp * 32 + ni * 8 + 2 * qlane;
                *(float2*)&Ls[mi * 16 + qid][px] = make_float2(d[mi][ni][0], d[mi][ni][1]);
                *(float2*)&Ls[mi * 16 + qid + 8][px] = make_float2(d[mi][ni][2], d[mi][ni][3]);
            }
        ssqs[wtid] = ssq;
    }
    __syncthreads();
    if (wg == 0) {
#pragma unroll
        for (int mi = 0; mi < 2; mi++)
#pragma unroll
            for (int ni = 0; ni < 4; ni++) {
                const int px = wp * 32 + ni * 8 + 2 * qlane;
                float2 u = *(float2*)&Ls[mi * 16 + qid][px];
                u.x += d[mi][ni][0]; u.y += d[mi][ni][1];
                *(float2*)&Ls[mi * 16 + qid][px] = u;
                float2 v = *(float2*)&Ls[mi * 16 + qid + 8][px];
                v.x += d[mi][ni][2]; v.y += d[mi][ni][3];
                *(float2*)&Ls[mi * 16 + qid + 8][px] = v;
            }
    }
    __syncthreads();

    // ---- softmax: wg0 thread owns pixel wtid ----
    if (wg == 0) {
        ssq += ssqs[wtid];
        const float r = 1.f / fmaxf(sqrtf(ssq), EPSN);
        float L[KC], m = -1e30f;
#pragma unroll
        for (int k = 0; k < KC; k++) {
            L[k] = Ls[k][wtid] * r;
            m = fmaxf(m, L[k]);
        }
        float ssum = 0.f;
#pragma unroll
        for (int k = 0; k < KC; k++) {
            L[k] = __expf(L[k] - m);
            ssum += L[k];
        }
        const float inv = 1.f / ssum;
        float* arp = g_ar + (size_t)n * KC * PD + pbase + wtid;
#pragma unroll
        for (int k = 0; k < KC; k++) {
            float a = L[k] * inv;
            arp[(size_t)k * PD] = a * r;
            float t = a;
            t += __shfl_xor_sync(0xffffffffu, t, 16);
            t += __shfl_xor_sync(0xffffffffu, t, 8);
            t += __shfl_xor_sync(0xffffffffu, t, 4);
            t += __shfl_xor_sync(0xffffffffu, t, 2);
            t += __shfl_xor_sync(0xffffffffu, t, 1);
            if (lane == 0) g_asp[(n * KC + k) * 32 + ptile * 4 + wp] = t;
        }
    }
}

// =====================================================================
// kb: vlad GEMM + fused per-image epilogue (last-block tail).
//   D[c=128, k=32] = sum_p x[c,p] * ar[k,p]
//   grid (8 ctiles, 16 n), 256 threads = 2 warpgroups (p-split).
//   tail: asum reduce + centroid subtract + row L2 + global L2 + write out.
// =====================================================================
#define KB_XSF 4608              // 128*36 floats per buffer
#define KB_ASF 1152              // 32*36 floats per buffer
#define KB_SMEM ((4 * KB_XSF + 4 * KB_ASF) * 4)

__global__ void __launch_bounds__(256, 1) kb(const float* __restrict__ x,
                                             const float* __restrict__ cent,
                                             float* __restrict__ out) {
    extern __shared__ float sm[];
    const int tid = threadIdx.x;
    const int wg = tid >> 7, wtid = tid & 127;
    const int lane = tid & 31, wp = wtid >> 5;
    const int qid = lane >> 2, qlane = lane & 3;
    const int ctile = blockIdx.x, n = blockIdx.y, cbase = ctile * 128;
    const float* xn = x + ((size_t)n * CD + cbase) * PD;
    const float* arn = g_ar + (size_t)n * KC * PD;
    const uint32_t smu = s2u(sm);

    float d[2][4][4];
#pragma unroll
    for (int mi = 0; mi < 2; mi++)
#pragma unroll
        for (int ni = 0; ni < 4; ni++)
#pragma unroll
            for (int r = 0; r < 4; r++) d[mi][ni][r] = 0.f;

#define KB_LD(gch, buf) do { \
        const int _p0 = (gch) * 32; \
        uint32_t _xd = smu + (unsigned)((wg * 2 + (buf)) * KB_XSF) * 4u; \
        _Pragma("unroll") \
        for (int i = 0; i < 8; i++) { \
            int idx = wtid + i * 128, c = idx >> 3, p4 = idx & 7; \
            CPA16(_xd + (unsigned)(c * 36 + p4 * 4) * 4u, xn + (size_t)c * PD + _p0 + p4 * 4); \
        } \
        uint32_t _ad = smu + (unsigned)(4 * KB_XSF + (wg * 2 + (buf)) * KB_ASF) * 4u; \
        _Pragma("unroll") \
        for (int i = 0; i < 2; i++) { \
            int idx = wtid + i * 128, k = idx >> 3, p4 = idx & 7; \
            CPA16(_ad + (unsigned)(k * 36 + p4 * 4) * 4u, arn + (size_t)k * PD + _p0 + p4 * 4); \
        } \
        CPC(); \
    } while (0)

    KB_LD(wg * 16 + 0, 0);
    KB_LD(wg * 16 + 1, 1);

    for (int ch = 0; ch < 16; ch++) {
        const int buf = ch & 1;
        if (ch < 15) CPW1(); else CPW0();
        __syncthreads();
        const float* xsb = sm + (wg * 2 + buf) * KB_XSF;
        const float* asb = sm + 4 * KB_XSF + (wg * 2 + buf) * KB_ASF;
#pragma unroll
        for (int s = 0; s < 4; s++) {
            uint32_t a[2][4], b[4][2];
            const int p0 = s * 8 + qlane;
#pragma unroll
            for (int mi = 0; mi < 2; mi++) {
                const int r0 = wp * 32 + mi * 16 + qid;
                a[mi][0] = __float_as_uint(xsb[r0 * 36 + p0]);
                a[mi][1] = __float_as_uint(xsb[(r0 + 8) * 36 + p0]);
                a[mi][2] = __float_as_uint(xsb[r0 * 36 + p0 + 4]);
                a[mi][3] = __float_as_uint(xsb[(r0 + 8) * 36 + p0 + 4]);
            }
#pragma unroll
            for (int ni = 0; ni < 4; ni++) {
                const int kk = ni * 8 + qid;
                b[ni][0] = __float_as_uint(asb[kk * 36 + p0]);
                b[ni][1] = __float_as_uint(asb[kk * 36 + p0 + 4]);
            }
#pragma unroll
            for (int mi = 0; mi < 2; mi++)
#pragma unroll
                for (int ni = 0; ni < 4; ni++) mma8(d[mi][ni], a[mi], b[ni]);
        }
        __syncthreads();
        if (ch + 2 < 16) KB_LD(wg * 16 + ch + 2, buf);
    }
#undef KB_LD

    // ---- combine wg partial D in smem, write g_v ----
    float (*Dsm)[34] = (float (*)[34])sm;
    if (wg == 1) {
#pragma unroll
        for (int mi = 0; mi < 2; mi++) {
            const int cl = wp * 32 + mi * 16 + qid;
#pragma unroll
            for (int ni = 0; ni < 4; ni++) {
                const int k0 = ni * 8 + 2 * qlane;
                *(float2*)&Dsm[cl][k0] = make_float2(d[mi][ni][0], d[mi][ni][1]);
                *(float2*)&Dsm[cl + 8][k0] = make_float2(d[mi][ni][2], d[mi][ni][3]);
            }
        }
    }
    __syncthreads();
    if (wg == 0) {
        float* gv = g_v + (size_t)n * KC * CD;
#pragma unroll
        for (int mi = 0; mi < 2; mi++) {
            const int cl = wp * 32 + mi * 16 + qid;
            const int c0 = cbase + cl;
#pragma unroll
            for (int ni = 0; ni < 4; ni++) {
                const int k0 = ni * 8 + 2 * qlane;
                float2 u = *(float2*)&Dsm[cl][k0];
                float2 v = *(float2*)&Dsm[cl + 8][k0];
                gv[(size_t)k0 * CD + c0] = u.x + d[mi][ni][0];
                gv[(size_t)(k0 + 1) * CD + c0] = u.y + d[mi][ni][1];
                gv[(size_t)k0 * CD + c0 + 8] = v.x + d[mi][ni][2];
                gv[(size_t)(k0 + 1) * CD + c0 + 8] = v.y + d[mi][ni][3];
            }
        }
    }

    // ---- completion ticket ----
    __shared__ unsigned s_old;
    __syncthreads();
    if (tid == 0) {
        __threadfence();
        s_old = atomicAdd(&g_ctr[n], 1u);
    }
    __syncthreads();
    if (s_old != 7) return;
    __threadfence();   // acquire all other blocks' g_v writes

    // ======== per-image tail (one block per image) ========
    __shared__ float s_asum[32], s_rinv[32], s_red[8];
    __shared__ float s_gg, s_ginv;
    const int l = tid & 31, wq = tid >> 5;
    if (tid == 0) s_gg = 0.f;
    if (tid < 32) {
        float t = 0.f;
#pragma unroll
        for (int i = 0; i < 32; i++) t += g_asp[(n * KC + tid) * 32 + i];
        s_asum[tid] = t;
    }
    __syncthreads();

    const float* gvn = g_v + (size_t)n * KC * CD;
    const int c4 = tid * 4;

    // pass 1: row sumsq -> rinv, accumulate global gg
    for (int k = 0; k < KC; k++) {
        float4 v = *(const float4*)(gvn + (size_t)k * CD + c4);
        float4 ce = *(const float4*)(cent + k * CD + c4);
        const float as = s_asum[k];
        v.x -= as * ce.x; v.y -= as * ce.y; v.z -= as * ce.z; v.w -= as * ce.w;
        float s = v.x * v.x + v.y * v.y + v.z * v.z + v.w * v.w;
        s += __shfl_xor_sync(0xffffffffu, s, 16);
        s += __shfl_xor_sync(0xffffffffu, s, 8);
        s += __shfl_xor_sync(0xffffffffu, s, 4);
        s += __shfl_xor_sync(0xffffffffu, s, 2);
        s += __shfl_xor_sync(0xffffffffu, s, 1);
        if (l == 0) s_red[wq] = s;
        __syncthreads();
        if (tid == 0) {
            float tot = 0.f;
#pragma unroll
            for (int i = 0; i < 8; i++) tot += s_red[i];
            float ri = 1.f / fmaxf(sqrtf(tot), EPSN);
            s_rinv[k] = ri;
            s_gg += tot * ri * ri;
        }
        __syncthreads();
    }
    if (tid == 0) s_ginv = 1.f / fmaxf(sqrtf(s_gg), EPSN);
    __syncthreads();

    // pass 2: scale and write out
    const float gi = s_ginv;
    float* on = out + (size_t)n * KC * CD;
    for (int k = 0; k < KC; k++) {
        const float sc = s_rinv[k] * gi;
        const float as = s_asum[k];
        float4 v = *(const float4*)(gvn + (size_t)k * CD + c4);
        float4 ce = *(const float4*)(cent + k * CD + c4);
        *(float4*)(on + (size_t)k * CD + c4) =
            make_float4((v.x - as * ce.x) * sc, (v.y - as * ce.y) * sc,
                        (v.z - as * ce.z) * sc, (v.w - as * ce.w) * sc);
    }
    if (tid == 0) g_ctr[n] = 0;   // reset for next graph replay
}

extern "C" void kernel_launch(void* const* d_in, const int* in_sizes, int n_in,
                              void* d_out, int out_size) {
    const float* x = (const float*)d_in[0];     // (16,1024,32,32)
    const float* w = (const float*)d_in[1];     // (32,1024)
    const float* cent = (const float*)d_in[2];  // (32,1024)
    float* out = (float*)d_out;                 // (16,32768)

    static int inited = 0;
    if (!inited) {
        cudaFuncSetAttribute(ka, cudaFuncAttributeMaxDynamicSharedMemorySize, KA_SMEM);
        cudaFuncSetAttribute(kb, cudaFuncAttributeMaxDynamicSharedMemorySize, KB_SMEM);
        inited = 1;
    }

    ka<<<dim3(8, 16), 256, KA_SMEM>>>(x, w);
    kb<<<dim3(8, 16), 256, KB_SMEM>>>(x, cent, out);
}

// round 11
// speedup vs baseline: 1.3076x; 1.3076x over previous
#include <cuda_runtime.h>
#include <math.h>
#include <stdint.h>

#define NI 16
#define CD 1024
#define PD 1024
#define KC 32
#define EPSN 1e-12f

// ---- scratch (static; no allocations allowed) ----
__device__ float g_ar[NI * KC * PD];     // softmax(a)*r  (kb's B operand)
__device__ float g_asp[NI * KC * 32];    // asum partials (ptile x warp)
__device__ float g_v[NI * KC * CD];      // raw vlad gemm D
__device__ unsigned g_ctr[NI];           // per-image completion tickets (self-resetting)

__device__ __forceinline__ uint32_t s2u(const void* p) {
    uint32_t a;
    asm("{ .reg .u64 t; cvta.to.shared.u64 t, %1; cvt.u32.u64 %0, t; }" : "=r"(a) : "l"(p));
    return a;
}

#define CPA16(d, s) asm volatile("cp.async.cg.shared.global [%0], [%1], 16;" :: "r"(d), "l"(s))
#define CPC()  asm volatile("cp.async.commit_group;")
#define CPW1() asm volatile("cp.async.wait_group 1;")
#define CPW0() asm volatile("cp.async.wait_group 0;")

// tf32 m16n8k8 row.col: D += A*B  (A: 4 regs, B: 2 regs, D: 4 floats)
__device__ __forceinline__ void mma8(float* d, const uint32_t* a, const uint32_t* b) {
    asm volatile(
        "mma.sync.aligned.m16n8k8.row.col.f32.tf32.tf32.f32 "
        "{%0,%1,%2,%3}, {%4,%5,%6,%7}, {%8,%9}, {%0,%1,%2,%3};"
        : "+f"(d[0]), "+f"(d[1]), "+f"(d[2]), "+f"(d[3])
        : "r"(a[0]), "r"(a[1]), "r"(a[2]), "r"(a[3]), "r"(b[0]), "r"(b[1]));
}

__device__ __forceinline__ float wred(float s) {
    s += __shfl_xor_sync(0xffffffffu, s, 16);
    s += __shfl_xor_sync(0xffffffffu, s, 8);
    s += __shfl_xor_sync(0xffffffffu, s, 4);
    s += __shfl_xor_sync(0xffffffffu, s, 2);
    s += __shfl_xor_sync(0xffffffffu, s, 1);
    return s;
}

// =====================================================================
// ka: logits GEMM + per-pixel norm + softmax, fused.
//   D[k=32, p=128] = sum_c w[k,c] * x[c,p]
//   grid (8 ptiles, 16 n), 256 threads = 2 warpgroups (c-split).
// =====================================================================
#define KA_XSF 4352              // 32*136 floats per buffer
#define KA_WSF 1152              // 32*36 floats per buffer
#define KA_SMEM ((4 * KA_XSF + 4 * KA_WSF) * 4)

__global__ void __launch_bounds__(256, 1) ka(const float* __restrict__ x,
                                             const float* __restrict__ w) {
    extern __shared__ float sm[];
    __shared__ float ssqs[128];
    const int tid = threadIdx.x;
    const int wg = tid >> 7, wtid = tid & 127;
    const int lane = tid & 31, wp = wtid >> 5;
    const int qid = lane >> 2, qlane = lane & 3;
    const int ptile = blockIdx.x, n = blockIdx.y, pbase = ptile * 128;
    const float* xn = x + (size_t)n * CD * PD + pbase;
    const uint32_t smu = s2u(sm);

    float d[2][4][4];
#pragma unroll
    for (int mi = 0; mi < 2; mi++)
#pragma unroll
        for (int ni = 0; ni < 4; ni++)
#pragma unroll
            for (int r = 0; r < 4; r++) d[mi][ni][r] = 0.f;
    float ssq = 0.f;

#define KA_LD(gch, buf) do { \
        const float* _x = xn + (size_t)(gch) * 32 * PD; \
        uint32_t _xd = smu + (unsigned)((wg * 2 + (buf)) * KA_XSF) * 4u; \
        _Pragma("unroll") \
        for (int i = 0; i < 8; i++) { \
            int idx = wtid + i * 128, c = idx >> 5, p4 = idx & 31; \
            CPA16(_xd + (unsigned)(c * 136 + p4 * 4) * 4u, _x + (size_t)c * PD + p4 * 4); \
        } \
        const float* _w = w + (gch) * 32; \
        uint32_t _wd = smu + (unsigned)(4 * KA_XSF + (wg * 2 + (buf)) * KA_WSF) * 4u; \
        _Pragma("unroll") \
        for (int i = 0; i < 2; i++) { \
            int idx = wtid + i * 128, k = idx >> 3, c4 = idx & 7; \
            CPA16(_wd + (unsigned)(k * 36 + c4 * 4) * 4u, _w + (size_t)k * CD + c4 * 4); \
        } \
        CPC(); \
    } while (0)

    KA_LD(wg * 16 + 0, 0);
    KA_LD(wg * 16 + 1, 1);

    for (int ch = 0; ch < 16; ch++) {
        const int buf = ch & 1;
        if (ch < 15) CPW1(); else CPW0();
        __syncthreads();
        const float* xsb = sm + (wg * 2 + buf) * KA_XSF;
        const float* wsb = sm + 4 * KA_XSF + (wg * 2 + buf) * KA_WSF;
#pragma unroll
        for (int c = 0; c < 32; c++) {
            float f = xsb[c * 136 + wtid];
            ssq = fmaf(f, f, ssq);
        }
#pragma unroll
        for (int s = 0; s < 4; s++) {
            uint32_t a[2][4], b[4][2];
            const int c0 = s * 8 + qlane;
#pragma unroll
            for (int mi = 0; mi < 2; mi++) {
                const int r0 = mi * 16 + qid;
                a[mi][0] = __float_as_uint(wsb[r0 * 36 + c0]);
                a[mi][1] = __float_as_uint(wsb[(r0 + 8) * 36 + c0]);
                a[mi][2] = __float_as_uint(wsb[r0 * 36 + c0 + 4]);
                a[mi][3] = __float_as_uint(wsb[(r0 + 8) * 36 + c0 + 4]);
            }
#pragma unroll
            for (int ni = 0; ni < 4; ni++) {
                const int pc = wp * 32 + ni * 8 + qid;
                b[ni][0] = __float_as_uint(xsb[c0 * 136 + pc]);
                b[ni][1] = __float_as_uint(xsb[(c0 + 4) * 136 + pc]);
            }
#pragma unroll
            for (int mi = 0; mi < 2; mi++)
#pragma unroll
                for (int ni = 0; ni < 4; ni++) mma8(d[mi][ni], a[mi], b[ni]);
        }
        __syncthreads();
        if (ch + 2 < 16) KA_LD(wg * 16 + ch + 2, buf);
    }
#undef KA_LD

    // ---- combine wg partial logits in smem: Ls[32 k][136] ----
    float (*Ls)[136] = (float (*)[136])sm;
    if (wg == 1) {
#pragma unroll
        for (int mi = 0; mi < 2; mi++)
#pragma unroll
            for (int ni = 0; ni < 4; ni++) {
                const int px = wp * 32 + ni * 8 + 2 * qlane;
                *(float2*)&Ls[mi * 16 + qid][px] = make_float2(d[mi][ni][0], d[mi][ni][1]);
                *(float2*)&Ls[mi * 16 + qid + 8][px] = make_float2(d[mi][ni][2], d[mi][ni][3]);
            }
        ssqs[wtid] = ssq;
    }
    __syncthreads();
    if (wg == 0) {
#pragma unroll
        for (int mi = 0; mi < 2; mi++)
#pragma unroll
            for (int ni = 0; ni < 4; ni++) {
                const int px = wp * 32 + ni * 8 + 2 * qlane;
                float2 u = *(float2*)&Ls[mi * 16 + qid][px];
                u.x += d[mi][ni][0]; u.y += d[mi][ni][1];
                *(float2*)&Ls[mi * 16 + qid][px] = u;
                float2 v = *(float2*)&Ls[mi * 16 + qid + 8][px];
                v.x += d[mi][ni][2]; v.y += d[mi][ni][3];
                *(float2*)&Ls[mi * 16 + qid + 8][px] = v;
            }
    }
    __syncthreads();

    // ---- softmax: wg0 thread owns pixel wtid ----
    if (wg == 0) {
        ssq += ssqs[wtid];
        const float r = 1.f / fmaxf(sqrtf(ssq), EPSN);
        float L[KC], m = -1e30f;
#pragma unroll
        for (int k = 0; k < KC; k++) {
            L[k] = Ls[k][wtid] * r;
            m = fmaxf(m, L[k]);
        }
        float ssum = 0.f;
#pragma unroll
        for (int k = 0; k < KC; k++) {
            L[k] = __expf(L[k] - m);
            ssum += L[k];
        }
        const float inv = 1.f / ssum;
        float* arp = g_ar + (size_t)n * KC * PD + pbase + wtid;
#pragma unroll
        for (int k = 0; k < KC; k++) {
            float a = L[k] * inv;
            arp[(size_t)k * PD] = a * r;
            float t = wred(a);
            if (lane == 0) g_asp[(n * KC + k) * 32 + ptile * 4 + wp] = t;
        }
    }
}

// =====================================================================
// kb: vlad GEMM + fused per-image epilogue (last-block tail, parallel).
//   D[c=128, k=32] = sum_p x[c,p] * ar[k,p]
//   grid (8 ctiles, 16 n), 256 threads = 2 warpgroups (p-split).
// =====================================================================
#define KB_XSF 4608              // 128*36 floats per buffer
#define KB_ASF 1152              // 32*36 floats per buffer
#define KB_SMEM ((4 * KB_XSF + 4 * KB_ASF) * 4)

__global__ void __launch_bounds__(256, 1) kb(const float* __restrict__ x,
                                             const float* __restrict__ cent,
                                             float* __restrict__ out) {
    extern __shared__ float sm[];
    const int tid = threadIdx.x;
    const int wg = tid >> 7, wtid = tid & 127;
    const int lane = tid & 31, wp = wtid >> 5;
    const int qid = lane >> 2, qlane = lane & 3;
    const int ctile = blockIdx.x, n = blockIdx.y, cbase = ctile * 128;
    const float* xn = x + ((size_t)n * CD + cbase) * PD;
    const float* arn = g_ar + (size_t)n * KC * PD;
    const uint32_t smu = s2u(sm);

    float d[2][4][4];
#pragma unroll
    for (int mi = 0; mi < 2; mi++)
#pragma unroll
        for (int ni = 0; ni < 4; ni++)
#pragma unroll
            for (int r = 0; r < 4; r++) d[mi][ni][r] = 0.f;

#define KB_LD(gch, buf) do { \
        const int _p0 = (gch) * 32; \
        uint32_t _xd = smu + (unsigned)((wg * 2 + (buf)) * KB_XSF) * 4u; \
        _Pragma("unroll") \
        for (int i = 0; i < 8; i++) { \
            int idx = wtid + i * 128, c = idx >> 3, p4 = idx & 7; \
            CPA16(_xd + (unsigned)(c * 36 + p4 * 4) * 4u, xn + (size_t)c * PD + _p0 + p4 * 4); \
        } \
        uint32_t _ad = smu + (unsigned)(4 * KB_XSF + (wg * 2 + (buf)) * KB_ASF) * 4u; \
        _Pragma("unroll") \
        for (int i = 0; i < 2; i++) { \
            int idx = wtid + i * 128, k = idx >> 3, p4 = idx & 7; \
            CPA16(_ad + (unsigned)(k * 36 + p4 * 4) * 4u, arn + (size_t)k * PD + _p0 + p4 * 4); \
        } \
        CPC(); \
    } while (0)

    KB_LD(wg * 16 + 0, 0);
    KB_LD(wg * 16 + 1, 1);

    for (int ch = 0; ch < 16; ch++) {
        const int buf = ch & 1;
        if (ch < 15) CPW1(); else CPW0();
        __syncthreads();
        const float* xsb = sm + (wg * 2 + buf) * KB_XSF;
        const float* asb = sm + 4 * KB_XSF + (wg * 2 + buf) * KB_ASF;
#pragma unroll
        for (int s = 0; s < 4; s++) {
            uint32_t a[2][4], b[4][2];
            const int p0 = s * 8 + qlane;
#pragma unroll
            for (int mi = 0; mi < 2; mi++) {
                const int r0 = wp * 32 + mi * 16 + qid;
                a[mi][0] = __float_as_uint(xsb[r0 * 36 + p0]);
                a[mi][1] = __float_as_uint(xsb[(r0 + 8) * 36 + p0]);
                a[mi][2] = __float_as_uint(xsb[r0 * 36 + p0 + 4]);
                a[mi][3] = __float_as_uint(xsb[(r0 + 8) * 36 + p0 + 4]);
            }
#pragma unroll
            for (int ni = 0; ni < 4; ni++) {
                const int kk = ni * 8 + qid;
                b[ni][0] = __float_as_uint(asb[kk * 36 + p0]);
                b[ni][1] = __float_as_uint(asb[kk * 36 + p0 + 4]);
            }
#pragma unroll
            for (int mi = 0; mi < 2; mi++)
#pragma unroll
                for (int ni = 0; ni < 4; ni++) mma8(d[mi][ni], a[mi], b[ni]);
        }
        __syncthreads();
        if (ch + 2 < 16) KB_LD(wg * 16 + ch + 2, buf);
    }
#undef KB_LD

    // ---- combine wg partial D in smem, write g_v ----
    float (*Dsm)[34] = (float (*)[34])sm;
    if (wg == 1) {
#pragma unroll
        for (int mi = 0; mi < 2; mi++) {
            const int cl = wp * 32 + mi * 16 + qid;
#pragma unroll
            for (int ni = 0; ni < 4; ni++) {
                const int k0 = ni * 8 + 2 * qlane;
                *(float2*)&Dsm[cl][k0] = make_float2(d[mi][ni][0], d[mi][ni][1]);
                *(float2*)&Dsm[cl + 8][k0] = make_float2(d[mi][ni][2], d[mi][ni][3]);
            }
        }
    }
    __syncthreads();
    if (wg == 0) {
        float* gv = g_v + (size_t)n * KC * CD;
#pragma unroll
        for (int mi = 0; mi < 2; mi++) {
            const int cl = wp * 32 + mi * 16 + qid;
            const int c0 = cbase + cl;
#pragma unroll
            for (int ni = 0; ni < 4; ni++) {
                const int k0 = ni * 8 + 2 * qlane;
                float2 u = *(float2*)&Dsm[cl][k0];
                float2 v = *(float2*)&Dsm[cl + 8][k0];
                gv[(size_t)k0 * CD + c0] = u.x + d[mi][ni][0];
                gv[(size_t)(k0 + 1) * CD + c0] = u.y + d[mi][ni][1];
                gv[(size_t)k0 * CD + c0 + 8] = v.x + d[mi][ni][2];
                gv[(size_t)(k0 + 1) * CD + c0 + 8] = v.y + d[mi][ni][3];
            }
        }
    }

    // ---- completion ticket ----
    __shared__ unsigned s_old;
    __syncthreads();
    if (tid == 0) {
        __threadfence();
        s_old = atomicAdd(&g_ctr[n], 1u);
    }
    __syncthreads();
    if (s_old != 7) return;
    __threadfence();   // acquire all other blocks' g_v writes

    // ======== per-image tail (one block per image; warp-parallel) ========
    __shared__ float s_asum[32], s_rowsq[32], s_sc[32];
    const int l = tid & 31, wq = tid >> 5;
    if (tid < 32) {
        float t = 0.f;
#pragma unroll
        for (int i = 0; i < 32; i++) t += g_asp[(n * KC + tid) * 32 + i];
        s_asum[tid] = t;
    }
    __syncthreads();

    const float* gvn = g_v + (size_t)n * KC * CD;

    // pass 1: warp wq owns rows {wq, wq+8, wq+16, wq+24}; no block barriers inside
#pragma unroll
    for (int kk = 0; kk < 4; kk++) {
        const int k = wq + kk * 8;
        const float as = s_asum[k];
        float s = 0.f;
#pragma unroll
        for (int i = 0; i < 8; i++) {
            const int c4 = (i * 32 + l) * 4;
            float4 v = *(const float4*)(gvn + (size_t)k * CD + c4);
            float4 ce = *(const float4*)(cent + k * CD + c4);
            v.x -= as * ce.x; v.y -= as * ce.y; v.z -= as * ce.z; v.w -= as * ce.w;
            s += v.x * v.x + v.y * v.y + v.z * v.z + v.w * v.w;
        }
        s = wred(s);
        if (l == 0) s_rowsq[k] = s;
    }
    __syncthreads();

    // warp 0: row inverse norms + global norm, all in registers
    if (tid < 32) {
        float tot = s_rowsq[tid];
        float ri = 1.f / fmaxf(sqrtf(tot), EPSN);
        float gg = wred(tot * ri * ri);          // same value on all lanes
        s_sc[tid] = ri * (1.f / fmaxf(sqrtf(gg), EPSN));
    }
    __syncthreads();

    // pass 2: scale and write out (same row ownership)
    float* on = out + (size_t)n * KC * CD;
#pragma unroll
    for (int kk = 0; kk < 4; kk++) {
        const int k = wq + kk * 8;
        const float as = s_asum[k];
        const float sc = s_sc[k];
#pragma unroll
        for (int i = 0; i < 8; i++) {
            const int c4 = (i * 32 + l) * 4;
            float4 v = *(const float4*)(gvn + (size_t)k * CD + c4);
            float4 ce = *(const float4*)(cent + k * CD + c4);
            *(float4*)(on + (size_t)k * CD + c4) =
                make_float4((v.x - as * ce.x) * sc, (v.y - as * ce.y) * sc,
                            (v.z - as * ce.z) * sc, (v.w - as * ce.w) * sc);
        }
    }
    if (tid == 0) g_ctr[n] = 0;   // reset for next graph replay
}

extern "C" void kernel_launch(void* const* d_in, const int* in_sizes, int n_in,
                              void* d_out, int out_size) {
    const float* x = (const float*)d_in[0];     // (16,1024,32,32)
    const float* w = (const float*)d_in[1];     // (32,1024)
    const float* cent = (const float*)d_in[2];  // (32,1024)
    float* out = (float*)d_out;                 // (16,32768)

    static int inited = 0;
    if (!inited) {
        cudaFuncSetAttribute(ka, cudaFuncAttributeMaxDynamicSharedMemorySize, KA_SMEM);
        cudaFuncSetAttribute(kb, cudaFuncAttributeMaxDynamicSharedMemorySize, KB_SMEM);
        inited = 1;
    }

    ka<<<dim3(8, 16), 256, KA_SMEM>>>(x, w);
    kb<<<dim3(8, 16), 256, KB_SMEM>>>(x, cent, out);
}

// round 12
// speedup vs baseline: 1.4225x; 1.0879x over previous
#include <cuda_runtime.h>
#include <math.h>
#include <stdint.h>

#define NI 16
#define CD 1024
#define PD 1024
#define KC 32
#define EPSN 1e-12f

// ---- scratch (static; no allocations allowed) ----
__device__ float g_ar[NI * KC * PD];     // softmax(a)*r  (kb's B operand)
__device__ float g_asp[NI * KC * 32];    // asum partials (ptile x warp)
__device__ float g_rsp[NI * 8 * KC];     // rowsq partials (ctile x k)
__device__ float g_sc[NI * KC];          // final per-row scale
__device__ unsigned g_ctr[NI];           // ticket 1 (rowsq partials done)
__device__ unsigned g_ctr2[NI];          // ticket 2 (output written)
__device__ unsigned g_flag[NI];          // sc ready

__device__ __forceinline__ uint32_t s2u(const void* p) {
    uint32_t a;
    asm("{ .reg .u64 t; cvta.to.shared.u64 t, %1; cvt.u32.u64 %0, t; }" : "=r"(a) : "l"(p));
    return a;
}

#define CPA16(d, s) asm volatile("cp.async.cg.shared.global [%0], [%1], 16;" :: "r"(d), "l"(s))
#define CPC()  asm volatile("cp.async.commit_group;")
#define CPW1() asm volatile("cp.async.wait_group 1;")
#define CPW0() asm volatile("cp.async.wait_group 0;")

// tf32 m16n8k8 row.col: D += A*B  (A: 4 regs, B: 2 regs, D: 4 floats)
__device__ __forceinline__ void mma8(float* d, const uint32_t* a, const uint32_t* b) {
    asm volatile(
        "mma.sync.aligned.m16n8k8.row.col.f32.tf32.tf32.f32 "
        "{%0,%1,%2,%3}, {%4,%5,%6,%7}, {%8,%9}, {%0,%1,%2,%3};"
        : "+f"(d[0]), "+f"(d[1]), "+f"(d[2]), "+f"(d[3])
        : "r"(a[0]), "r"(a[1]), "r"(a[2]), "r"(a[3]), "r"(b[0]), "r"(b[1]));
}

__device__ __forceinline__ float wred(float s) {
    s += __shfl_xor_sync(0xffffffffu, s, 16);
    s += __shfl_xor_sync(0xffffffffu, s, 8);
    s += __shfl_xor_sync(0xffffffffu, s, 4);
    s += __shfl_xor_sync(0xffffffffu, s, 2);
    s += __shfl_xor_sync(0xffffffffu, s, 1);
    return s;
}

// =====================================================================
// ka: logits GEMM + per-pixel norm + softmax, fused.
//   D[k=32, p=128] = sum_c w[k,c] * x[c,p]
//   grid (8 ptiles, 16 n), 256 threads = 2 warpgroups (c-split).
// =====================================================================
#define KA_XSF 4352              // 32*136 floats per buffer
#define KA_WSF 1152              // 32*36 floats per buffer
#define KA_SMEM ((4 * KA_XSF + 4 * KA_WSF) * 4)

__global__ void __launch_bounds__(256, 1) ka(const float* __restrict__ x,
                                             const float* __restrict__ w) {
    extern __shared__ float sm[];
    __shared__ float ssqs[128];
    const int tid = threadIdx.x;
    const int wg = tid >> 7, wtid = tid & 127;
    const int lane = tid & 31, wp = wtid >> 5;
    const int qid = lane >> 2, qlane = lane & 3;
    const int ptile = blockIdx.x, n = blockIdx.y, pbase = ptile * 128;
    const float* xn = x + (size_t)n * CD * PD + pbase;
    const uint32_t smu = s2u(sm);

    float d[2][4][4];
#pragma unroll
    for (int mi = 0; mi < 2; mi++)
#pragma unroll
        for (int ni = 0; ni < 4; ni++)
#pragma unroll
            for (int r = 0; r < 4; r++) d[mi][ni][r] = 0.f;
    float ssq = 0.f;

#define KA_LD(gch, buf) do { \
        const float* _x = xn + (size_t)(gch) * 32 * PD; \
        uint32_t _xd = smu + (unsigned)((wg * 2 + (buf)) * KA_XSF) * 4u; \
        _Pragma("unroll") \
        for (int i = 0; i < 8; i++) { \
            int idx = wtid + i * 128, c = idx >> 5, p4 = idx & 31; \
            CPA16(_xd + (unsigned)(c * 136 + p4 * 4) * 4u, _x + (size_t)c * PD + p4 * 4); \
        } \
        const float* _w = w + (gch) * 32; \
        uint32_t _wd = smu + (unsigned)(4 * KA_XSF + (wg * 2 + (buf)) * KA_WSF) * 4u; \
        _Pragma("unroll") \
        for (int i = 0; i < 2; i++) { \
            int idx = wtid + i * 128, k = idx >> 3, c4 = idx & 7; \
            CPA16(_wd + (unsigned)(k * 36 + c4 * 4) * 4u, _w + (size_t)k * CD + c4 * 4); \
        } \
        CPC(); \
    } while (0)

    KA_LD(wg * 16 + 0, 0);
    KA_LD(wg * 16 + 1, 1);

    for (int ch = 0; ch < 16; ch++) {
        const int buf = ch & 1;
        if (ch < 15) CPW1(); else CPW0();
        __syncthreads();
        const float* xsb = sm + (wg * 2 + buf) * KA_XSF;
        const float* wsb = sm + 4 * KA_XSF + (wg * 2 + buf) * KA_WSF;
#pragma unroll
        for (int c = 0; c < 32; c++) {
            float f = xsb[c * 136 + wtid];
            ssq = fmaf(f, f, ssq);
        }
#pragma unroll
        for (int s = 0; s < 4; s++) {
            uint32_t a[2][4], b[4][2];
            const int c0 = s * 8 + qlane;
#pragma unroll
            for (int mi = 0; mi < 2; mi++) {
                const int r0 = mi * 16 + qid;
                a[mi][0] = __float_as_uint(wsb[r0 * 36 + c0]);
                a[mi][1] = __float_as_uint(wsb[(r0 + 8) * 36 + c0]);
                a[mi][2] = __float_as_uint(wsb[r0 * 36 + c0 + 4]);
                a[mi][3] = __float_as_uint(wsb[(r0 + 8) * 36 + c0 + 4]);
            }
#pragma unroll
            for (int ni = 0; ni < 4; ni++) {
                const int pc = wp * 32 + ni * 8 + qid;
                b[ni][0] = __float_as_uint(xsb[c0 * 136 + pc]);
                b[ni][1] = __float_as_uint(xsb[(c0 + 4) * 136 + pc]);
            }
#pragma unroll
            for (int mi = 0; mi < 2; mi++)
#pragma unroll
                for (int ni = 0; ni < 4; ni++) mma8(d[mi][ni], a[mi], b[ni]);
        }
        __syncthreads();
        if (ch + 2 < 16) KA_LD(wg * 16 + ch + 2, buf);
    }
#undef KA_LD

    // ---- combine wg partial logits in smem: Ls[32 k][136] ----
    float (*Ls)[136] = (float (*)[136])sm;
    if (wg == 1) {
#pragma unroll
        for (int mi = 0; mi < 2; mi++)
#pragma unroll
            for (int ni = 0; ni < 4; ni++) {
                const int px = wp * 32 + ni * 8 + 2 * qlane;
                *(float2*)&Ls[mi * 16 + qid][px] = make_float2(d[mi][ni][0], d[mi][ni][1]);
                *(float2*)&Ls[mi * 16 + qid + 8][px] = make_float2(d[mi][ni][2], d[mi][ni][3]);
            }
        ssqs[wtid] = ssq;
    }
    __syncthreads();
    if (wg == 0) {
#pragma unroll
        for (int mi = 0; mi < 2; mi++)
#pragma unroll
            for (int ni = 0; ni < 4; ni++) {
                const int px = wp * 32 + ni * 8 + 2 * qlane;
                float2 u = *(float2*)&Ls[mi * 16 + qid][px];
                u.x += d[mi][ni][0]; u.y += d[mi][ni][1];
                *(float2*)&Ls[mi * 16 + qid][px] = u;
                float2 v = *(float2*)&Ls[mi * 16 + qid + 8][px];
                v.x += d[mi][ni][2]; v.y += d[mi][ni][3];
                *(float2*)&Ls[mi * 16 + qid + 8][px] = v;
            }
    }
    __syncthreads();

    // ---- softmax: wg0 thread owns pixel wtid ----
    if (wg == 0) {
        ssq += ssqs[wtid];
        const float r = 1.f / fmaxf(sqrtf(ssq), EPSN);
        float L[KC], m = -1e30f;
#pragma unroll
        for (int k = 0; k < KC; k++) {
            L[k] = Ls[k][wtid] * r;
            m = fmaxf(m, L[k]);
        }
        float ssum = 0.f;
#pragma unroll
        for (int k = 0; k < KC; k++) {
            L[k] = __expf(L[k] - m);
            ssum += L[k];
        }
        const float inv = 1.f / ssum;
        float* arp = g_ar + (size_t)n * KC * PD + pbase + wtid;
#pragma unroll
        for (int k = 0; k < KC; k++) {
            float a = L[k] * inv;
            arp[(size_t)k * PD] = a * r;
            float t = wred(a);
            if (lane == 0) g_asp[(n * KC + k) * 32 + ptile * 4 + wp] = t;
        }
    }
}

// =====================================================================
// kb: vlad GEMM + register-resident epilogue (grid-cooperative).
//   D[c=128, k=32] = sum_p x[c,p] * ar[k,p]
//   grid (8 ctiles, 16 n), 256 threads = 2 warpgroups (p-split).
//   All 128 blocks resident (1 CTA/SM) -> flag spin is deadlock-free.
// =====================================================================
#define KB_XSF 4608              // 128*36 floats per buffer
#define KB_ASF 1152              // 32*36 floats per buffer
#define KB_SMEM ((4 * KB_XSF + 4 * KB_ASF) * 4)

__global__ void __launch_bounds__(256, 1) kb(const float* __restrict__ x,
                                             const float* __restrict__ cent,
                                             float* __restrict__ out) {
    extern __shared__ float sm[];
    __shared__ float s_asum[32], s_sc2[32], srq[4][32];
    __shared__ unsigned s_old;
    const int tid = threadIdx.x;
    const int wg = tid >> 7, wtid = tid & 127;
    const int lane = tid & 31, wp = wtid >> 5;
    const int qid = lane >> 2, qlane = lane & 3;
    const int ctile = blockIdx.x, n = blockIdx.y, cbase = ctile * 128;
    const float* xn = x + ((size_t)n * CD + cbase) * PD;
    const float* arn = g_ar + (size_t)n * KC * PD;
    const uint32_t smu = s2u(sm);

    // asum for this image (g_asp complete: previous launch)
    if (tid < 32) {
        float t = 0.f;
#pragma unroll
        for (int i = 0; i < 32; i++) t += g_asp[(n * KC + tid) * 32 + i];
        s_asum[tid] = t;
    }

    float d[2][4][4];
#pragma unroll
    for (int mi = 0; mi < 2; mi++)
#pragma unroll
        for (int ni = 0; ni < 4; ni++)
#pragma unroll
            for (int r = 0; r < 4; r++) d[mi][ni][r] = 0.f;

#define KB_LD(gch, buf) do { \
        const int _p0 = (gch) * 32; \
        uint32_t _xd = smu + (unsigned)((wg * 2 + (buf)) * KB_XSF) * 4u; \
        _Pragma("unroll") \
        for (int i = 0; i < 8; i++) { \
            int idx = wtid + i * 128, c = idx >> 3, p4 = idx & 7; \
            CPA16(_xd + (unsigned)(c * 36 + p4 * 4) * 4u, xn + (size_t)c * PD + _p0 + p4 * 4); \
        } \
        uint32_t _ad = smu + (unsigned)(4 * KB_XSF + (wg * 2 + (buf)) * KB_ASF) * 4u; \
        _Pragma("unroll") \
        for (int i = 0; i < 2; i++) { \
            int idx = wtid + i * 128, k = idx >> 3, p4 = idx & 7; \
            CPA16(_ad + (unsigned)(k * 36 + p4 * 4) * 4u, arn + (size_t)k * PD + _p0 + p4 * 4); \
        } \
        CPC(); \
    } while (0)

    KB_LD(wg * 16 + 0, 0);
    KB_LD(wg * 16 + 1, 1);

    for (int ch = 0; ch < 16; ch++) {
        const int buf = ch & 1;
        if (ch < 15) CPW1(); else CPW0();
        __syncthreads();
        const float* xsb = sm + (wg * 2 + buf) * KB_XSF;
        const float* asb = sm + 4 * KB_XSF + (wg * 2 + buf) * KB_ASF;
#pragma unroll
        for (int s = 0; s < 4; s++) {
            uint32_t a[2][4], b[4][2];
            const int p0 = s * 8 + qlane;
#pragma unroll
            for (int mi = 0; mi < 2; mi++) {
                const int r0 = wp * 32 + mi * 16 + qid;
                a[mi][0] = __float_as_uint(xsb[r0 * 36 + p0]);
                a[mi][1] = __float_as_uint(xsb[(r0 + 8) * 36 + p0]);
                a[mi][2] = __float_as_uint(xsb[r0 * 36 + p0 + 4]);
                a[mi][3] = __float_as_uint(xsb[(r0 + 8) * 36 + p0 + 4]);
            }
#pragma unroll
            for (int ni = 0; ni < 4; ni++) {
                const int kk = ni * 8 + qid;
                b[ni][0] = __float_as_uint(asb[kk * 36 + p0]);
                b[ni][1] = __float_as_uint(asb[kk * 36 + p0 + 4]);
            }
#pragma unroll
            for (int mi = 0; mi < 2; mi++)
#pragma unroll
                for (int ni = 0; ni < 4; ni++) mma8(d[mi][ni], a[mi], b[ni]);
        }
        __syncthreads();
        if (ch + 2 < 16) KB_LD(wg * 16 + ch + 2, buf);
    }
#undef KB_LD

    // ---- combine wg partials: wg1 dumps to smem, wg0 accumulates into regs ----
    float (*Dsm)[34] = (float (*)[34])sm;
    if (wg == 1) {
#pragma unroll
        for (int mi = 0; mi < 2; mi++) {
            const int cl = wp * 32 + mi * 16 + qid;
#pragma unroll
            for (int ni = 0; ni < 4; ni++) {
                const int k0 = ni * 8 + 2 * qlane;
                *(float2*)&Dsm[cl][k0] = make_float2(d[mi][ni][0], d[mi][ni][1]);
                *(float2*)&Dsm[cl + 8][k0] = make_float2(d[mi][ni][2], d[mi][ni][3]);
            }
        }
    }
    __syncthreads();
    if (wg == 0) {
#pragma unroll
        for (int mi = 0; mi < 2; mi++) {
            const int cl = wp * 32 + mi * 16 + qid;
#pragma unroll
            for (int ni = 0; ni < 4; ni++) {
                const int k0 = ni * 8 + 2 * qlane;
                float2 u = *(float2*)&Dsm[cl][k0];
                float2 v = *(float2*)&Dsm[cl + 8][k0];
                d[mi][ni][0] += u.x; d[mi][ni][1] += u.y;
                d[mi][ni][2] += v.x; d[mi][ni][3] += v.y;
            }
        }
    }
    __syncthreads();

    // ---- stage centroid tile to smem: cs[32 k][132] (c slice of this block) ----
    float (*cs)[132] = (float (*)[132])sm;
    for (int i = tid; i < 32 * 128; i += 256) {
        int k = i >> 7, cc = i & 127;
        cs[k][cc] = cent[k * CD + cbase + cc];
    }
    __syncthreads();

    // ---- subtract asum*cent in regs + per-k rowsq partials ----
    if (wg == 0) {
        float rq[4][2];
#pragma unroll
        for (int ni = 0; ni < 4; ni++) { rq[ni][0] = 0.f; rq[ni][1] = 0.f; }
#pragma unroll
        for (int mi = 0; mi < 2; mi++) {
            const int cl = wp * 32 + mi * 16 + qid;
#pragma unroll
            for (int ni = 0; ni < 4; ni++) {
                const int k0 = ni * 8 + 2 * qlane;
                const float as0 = s_asum[k0], as1 = s_asum[k0 + 1];
                d[mi][ni][0] -= as0 * cs[k0][cl];
                d[mi][ni][1] -= as1 * cs[k0 + 1][cl];
                d[mi][ni][2] -= as0 * cs[k0][cl + 8];
                d[mi][ni][3] -= as1 * cs[k0 + 1][cl + 8];
                rq[ni][0] += d[mi][ni][0] * d[mi][ni][0] + d[mi][ni][2] * d[mi][ni][2];
                rq[ni][1] += d[mi][ni][1] * d[mi][ni][1] + d[mi][ni][3] * d[mi][ni][3];
            }
        }
        // reduce over qid (c direction) within warp
#pragma unroll
        for (int ni = 0; ni < 4; ni++)
#pragma unroll
            for (int b = 0; b < 2; b++) {
                float s = rq[ni][b];
                s += __shfl_xor_sync(0xffffffffu, s, 4);
                s += __shfl_xor_sync(0xffffffffu, s, 8);
                s += __shfl_xor_sync(0xffffffffu, s, 16);
                if (qid == 0) srq[wp][ni * 8 + 2 * qlane + b] = s;
            }
    }
    __syncthreads();
    if (tid < 32) {
        float pr = srq[0][tid] + srq[1][tid] + srq[2][tid] + srq[3][tid];
        g_rsp[(n * 8 + ctile) * 32 + tid] = pr;
    }
    __syncthreads();
    if (tid == 0) {
        __threadfence();
        s_old = atomicAdd(&g_ctr[n], 1u);
    }
    __syncthreads();

    if (s_old == 7u) {
        // last block of this image: finalize scales
        __threadfence();
        if (tid < 32) {
            float tot = 0.f;
#pragma unroll
            for (int ct = 0; ct < 8; ct++) tot += g_rsp[(n * 8 + ct) * 32 + tid];
            float ri = 1.f / fmaxf(sqrtf(tot), EPSN);
            float gg = wred(tot * ri * ri);
            g_sc[n * 32 + tid] = ri * (1.f / fmaxf(sqrtf(gg), EPSN));
        }
        __syncthreads();
        if (tid == 0) {
            __threadfence();
            atomicExch(&g_flag[n], 1u);
        }
    }

    // spin for sc (all 128 blocks resident -> safe)
    if (tid == 0) {
        while (atomicOr(&g_flag[n], 0u) == 0u) __nanosleep(64);
        __threadfence();
    }
    __syncthreads();
    if (tid < 32) s_sc2[tid] = g_sc[n * 32 + tid];
    __syncthreads();

    // ---- scale register tile and write out ----
    if (wg == 0) {
        float* on = out + (size_t)n * KC * CD + cbase;
#pragma unroll
        for (int mi = 0; mi < 2; mi++) {
            const int cl = wp * 32 + mi * 16 + qid;
#pragma unroll
            for (int ni = 0; ni < 4; ni++) {
                const int k0 = ni * 8 + 2 * qlane;
                const float sc0 = s_sc2[k0], sc1 = s_sc2[k0 + 1];
                on[(size_t)k0 * CD + cl] = d[mi][ni][0] * sc0;
                on[(size_t)(k0 + 1) * CD + cl] = d[mi][ni][1] * sc1;
                on[(size_t)k0 * CD + cl + 8] = d[mi][ni][2] * sc0;
                on[(size_t)(k0 + 1) * CD + cl + 8] = d[mi][ni][3] * sc1;
            }
        }
    }
    __syncthreads();
    if (tid == 0) {
        unsigned o2 = atomicAdd(&g_ctr2[n], 1u);
        if (o2 == 7u) {   // all 8 blocks done reading sc/flag: reset for next replay
            g_flag[n] = 0u;
            g_ctr[n] = 0u;
            g_ctr2[n] = 0u;
        }
    }
}

extern "C" void kernel_launch(void* const* d_in, const int* in_sizes, int n_in,
                              void* d_out, int out_size) {
    const float* x = (const float*)d_in[0];     // (16,1024,32,32)
    const float* w = (const float*)d_in[1];     // (32,1024)
    const float* cent = (const float*)d_in[2];  // (32,1024)
    float* out = (float*)d_out;                 // (16,32768)

    static int inited = 0;
    if (!inited) {
        cudaFuncSetAttribute(ka, cudaFuncAttributeMaxDynamicSharedMemorySize, KA_SMEM);
        cudaFuncSetAttribute(kb, cudaFuncAttributeMaxDynamicSharedMemorySize, KB_SMEM);
        inited = 1;
    }

    ka<<<dim3(8, 16), 256, KA_SMEM>>>(x, w);
    kb<<<dim3(8, 16), 256, KB_SMEM>>>(x, cent, out);
}